// round 1
// baseline (speedup 1.0000x reference)
#include <cuda_runtime.h>
#include <cuda_bf16.h>
#include <math.h>

// Problem constants
#define T_SEQ 4096
#define D_MODEL 2048
#define DH 128
#define NH 16
#define NKV 4
#define DKV 512   // NKV * DH

// ---------------------------------------------------------------------------
// Scratch (device globals — no allocations allowed)
// ---------------------------------------------------------------------------
__device__ float g_Q[(size_t)NH * DH * T_SEQ];   // [h][d][t]  (d-major for attention)
__device__ float g_K[(size_t)NKV * DH * T_SEQ];  // [kh][d][t]
__device__ float g_V[(size_t)T_SEQ * DKV];       // [t][kh*128+d]
__device__ float g_C[(size_t)T_SEQ * D_MODEL];   // attention context [t][h*128+d]

// ---------------------------------------------------------------------------
// SGEMM: C(MxN) = A(MxK) @ B(KxN), fp32, 128x128x8 tiles, 256 threads,
// 8x8 per-thread microtile. TC=0: row-major C. TC=1: write C^T (C[n*M+m]).
// Requires M%128==0, N%128==0, K%8==0.
// ---------------------------------------------------------------------------
template<int TC>
__global__ __launch_bounds__(256)
void sgemm128(const float* __restrict__ A, const float* __restrict__ B,
              float* __restrict__ C, int M, int N, int K)
{
    __shared__ float As[8][132];   // padded: conflict-free transpose writes
    __shared__ float Bs[8][128];

    const int tid = threadIdx.x;
    const int tx  = tid & 15;
    const int ty  = tid >> 4;
    const int m0  = blockIdx.y * 128;
    const int n0  = blockIdx.x * 128;

    const int arow = tid >> 1;           // 0..127
    const int acol = (tid & 1) << 2;     // 0 or 4
    const int brow = tid >> 5;           // 0..7
    const int bcol = (tid & 31) << 2;    // 0..124

    const float* Ap = A + (size_t)(m0 + arow) * K + acol;
    const float* Bp = B + (size_t)brow * N + n0 + bcol;

    float acc[8][8];
    #pragma unroll
    for (int i = 0; i < 8; i++)
        #pragma unroll
        for (int j = 0; j < 8; j++) acc[i][j] = 0.f;

    const int nk = K >> 3;
    for (int kt = 0; kt < nk; kt++) {
        float4 av = *(const float4*)Ap;
        float4 bv = *(const float4*)Bp;
        __syncthreads();
        As[acol + 0][arow] = av.x;
        As[acol + 1][arow] = av.y;
        As[acol + 2][arow] = av.z;
        As[acol + 3][arow] = av.w;
        *(float4*)&Bs[brow][bcol] = bv;
        __syncthreads();
        #pragma unroll
        for (int k = 0; k < 8; k++) {
            float4 a0 = *(const float4*)&As[k][ty << 2];
            float4 a1 = *(const float4*)&As[k][(ty << 2) + 64];
            float4 b0 = *(const float4*)&Bs[k][tx << 2];
            float4 b1 = *(const float4*)&Bs[k][(tx << 2) + 64];
            float ar[8] = {a0.x, a0.y, a0.z, a0.w, a1.x, a1.y, a1.z, a1.w};
            float br[8] = {b0.x, b0.y, b0.z, b0.w, b1.x, b1.y, b1.z, b1.w};
            #pragma unroll
            for (int i = 0; i < 8; i++)
                #pragma unroll
                for (int j = 0; j < 8; j++)
                    acc[i][j] = fmaf(ar[i], br[j], acc[i][j]);
        }
        Ap += 8;
        Bp += (size_t)8 * N;
    }

    #pragma unroll
    for (int hm = 0; hm < 2; hm++)
        #pragma unroll
        for (int jr = 0; jr < 4; jr++) {
            int m = m0 + hm * 64 + (ty << 2) + jr;
            #pragma unroll
            for (int hn = 0; hn < 2; hn++) {
                int n = n0 + hn * 64 + (tx << 2);
                int ai = hm * 4 + jr;
                if (TC == 0) {
                    float4 v = make_float4(acc[ai][hn*4+0], acc[ai][hn*4+1],
                                           acc[ai][hn*4+2], acc[ai][hn*4+3]);
                    *(float4*)&C[(size_t)m * N + n] = v;
                } else {
                    C[(size_t)(n + 0) * M + m] = acc[ai][hn*4+0];
                    C[(size_t)(n + 1) * M + m] = acc[ai][hn*4+1];
                    C[(size_t)(n + 2) * M + m] = acc[ai][hn*4+2];
                    C[(size_t)(n + 3) * M + m] = acc[ai][hn*4+3];
                }
            }
        }
}

// ---------------------------------------------------------------------------
// RoPE in-place on d-major Q [h][d][t] and K [kh][d][t].
// One thread per (head, freq-pair, t). Matches reference fp32 quantization:
// omega computed in double then cast to fp32; angle = fp32(t * omega).
// ---------------------------------------------------------------------------
__global__ void rope_kernel(float* __restrict__ Qd, float* __restrict__ Kd)
{
    int idx = blockIdx.x * blockDim.x + threadIdx.x;
    const int total = (NH + NKV) * (DH / 2) * T_SEQ;
    if (idx >= total) return;
    int t    = idx & (T_SEQ - 1);
    int rest = idx >> 12;                       // T_SEQ = 2^12
    float* base;
    int i;
    if (rest < NH * (DH / 2)) {
        int h = rest >> 6;  i = rest & 63;
        base = Qd + (size_t)(h * DH + 2 * i) * T_SEQ + t;
    } else {
        rest -= NH * (DH / 2);
        int h = rest >> 6;  i = rest & 63;
        base = Kd + (size_t)(h * DH + 2 * i) * T_SEQ + t;
    }
    float omega = (float)(1.0 / pow(10000.0, (double)(2 * i) / (double)DH));
    float ang = (float)t * omega;
    float s, c;
    sincosf(ang, &s, &c);
    float x0 = base[0];
    float x1 = base[T_SEQ];
    base[0]     = x0 * c - x1 * s;
    base[T_SEQ] = x0 * s + x1 * c;
}

// ---------------------------------------------------------------------------
// Flash attention, fp32, online softmax, causal, GQA (h -> h>>2).
// Block: 256 threads (16x16), q-tile 64, kv-tile 64.
// Qs/Ks stored d-major [128][68] (pad 68 keeps float4 alignment, kills
// transpose-write conflicts). Vs row-major [64][128]. P staged transposed.
// ---------------------------------------------------------------------------
#define QSTR 68
#define PSTR 68
#define FLASH_SMEM_FLOATS (128*QSTR*2 + 64*128 + 64*PSTR)
#define FLASH_SMEM_BYTES  (FLASH_SMEM_FLOATS * 4)

__global__ __launch_bounds__(256, 1)
void flash_kernel(const float* __restrict__ Qd, const float* __restrict__ Kd,
                  const float* __restrict__ Vt, float* __restrict__ Ctx)
{
    extern __shared__ float sm[];
    float* Qs = sm;                       // [128][QSTR]
    float* Ks = Qs + 128 * QSTR;          // [128][QSTR]
    float* Vs = Ks + 128 * QSTR;          // [64][128]
    float* Pt = Vs + 64 * 128;            // [64][PSTR]  (P transposed: [c][r])

    const int tid = threadIdx.x;
    const int tx  = tid & 15;
    const int ty  = tid >> 4;
    const int qt  = gridDim.x - 1 - blockIdx.x;   // big tiles scheduled first
    const int h   = blockIdx.y;
    const int kh  = h >> 2;
    const int qbase = qt * 64;

    const float* Qh = Qd + (size_t)h  * DH * T_SEQ;
    const float* Kh = Kd + (size_t)kh * DH * T_SEQ;

    // Load Q tile -> Qs[d][r], coalesced over t
    #pragma unroll
    for (int it = 0; it < 8; it++) {
        int idx = it * 256 + tid;
        int d   = idx >> 4;
        int rr  = (idx & 15) << 2;
        *(float4*)&Qs[d * QSTR + rr] = *(const float4*)&Qh[(size_t)d * T_SEQ + qbase + rr];
    }

    float m_i[4], l_i[4], Oc[4][8];
    #pragma unroll
    for (int jr = 0; jr < 4; jr++) {
        m_i[jr] = -1e30f;
        l_i[jr] = 0.f;
        #pragma unroll
        for (int c = 0; c < 8; c++) Oc[jr][c] = 0.f;
    }

    const float SCALE = 0.08838834764831843f;  // 1/sqrt(128)
    const int ntiles = qt + 1;

    for (int jt = 0; jt < ntiles; jt++) {
        const int kbase = jt * 64;
        __syncthreads();   // previous iter's smem reads done (also covers Q load)

        // K tile -> Ks[d][c]
        #pragma unroll
        for (int it = 0; it < 8; it++) {
            int idx = it * 256 + tid;
            int d   = idx >> 4;
            int rr  = (idx & 15) << 2;
            *(float4*)&Ks[d * QSTR + rr] = *(const float4*)&Kh[(size_t)d * T_SEQ + kbase + rr];
        }
        // V tile -> Vs[c][dd]
        #pragma unroll
        for (int it = 0; it < 8; it++) {
            int idx = it * 256 + tid;
            int r   = idx >> 5;
            int dd  = (idx & 31) << 2;
            *(float4*)&Vs[r * 128 + dd] =
                *(const float4*)&Vt[(size_t)(kbase + r) * DKV + kh * DH + dd];
        }
        __syncthreads();

        // S = Q @ K^T  (64x64, each thread 4x4)
        float S[4][4];
        #pragma unroll
        for (int a = 0; a < 4; a++)
            #pragma unroll
            for (int b = 0; b < 4; b++) S[a][b] = 0.f;

        #pragma unroll 8
        for (int d = 0; d < 128; d++) {
            float4 qa = *(const float4*)&Qs[d * QSTR + (ty << 2)];
            float4 ka = *(const float4*)&Ks[d * QSTR + (tx << 2)];
            float qr[4] = {qa.x, qa.y, qa.z, qa.w};
            float kr[4] = {ka.x, ka.y, ka.z, ka.w};
            #pragma unroll
            for (int a = 0; a < 4; a++)
                #pragma unroll
                for (int b = 0; b < 4; b++)
                    S[a][b] = fmaf(qr[a], kr[b], S[a][b]);
        }

        #pragma unroll
        for (int a = 0; a < 4; a++)
            #pragma unroll
            for (int b = 0; b < 4; b++) S[a][b] *= SCALE;

        if (jt == qt) {  // diagonal tile: mask c > r
            #pragma unroll
            for (int a = 0; a < 4; a++)
                #pragma unroll
                for (int b = 0; b < 4; b++)
                    if ((tx << 2) + b > (ty << 2) + a) S[a][b] = -1e30f;
        }

        // online softmax (row = 4*ty + jr; reduce across the 16 tx lanes)
        #pragma unroll
        for (int jr = 0; jr < 4; jr++) {
            float mx = fmaxf(fmaxf(S[jr][0], S[jr][1]), fmaxf(S[jr][2], S[jr][3]));
            #pragma unroll
            for (int o = 1; o < 16; o <<= 1)
                mx = fmaxf(mx, __shfl_xor_sync(0xffffffffu, mx, o));
            float mn = fmaxf(m_i[jr], mx);
            float sc = __expf(m_i[jr] - mn);
            m_i[jr] = mn;
            float rs = 0.f;
            #pragma unroll
            for (int jc = 0; jc < 4; jc++) {
                float p = __expf(S[jr][jc] - mn);
                S[jr][jc] = p;
                rs += p;
            }
            #pragma unroll
            for (int o = 1; o < 16; o <<= 1)
                rs += __shfl_xor_sync(0xffffffffu, rs, o);
            l_i[jr] = l_i[jr] * sc + rs;
            #pragma unroll
            for (int c = 0; c < 8; c++) Oc[jr][c] *= sc;
            #pragma unroll
            for (int jc = 0; jc < 4; jc++)
                Pt[((tx << 2) + jc) * PSTR + (ty << 2) + jr] = S[jr][jc];
        }
        __syncthreads();

        // O += P @ V
        #pragma unroll 4
        for (int c = 0; c < 64; c++) {
            float4 pa = *(const float4*)&Pt[c * PSTR + (ty << 2)];
            float4 v0 = *(const float4*)&Vs[c * 128 + (tx << 2)];
            float4 v1 = *(const float4*)&Vs[c * 128 + 64 + (tx << 2)];
            float pr[4] = {pa.x, pa.y, pa.z, pa.w};
            float vr[8] = {v0.x, v0.y, v0.z, v0.w, v1.x, v1.y, v1.z, v1.w};
            #pragma unroll
            for (int jr = 0; jr < 4; jr++)
                #pragma unroll
                for (int cc = 0; cc < 8; cc++)
                    Oc[jr][cc] = fmaf(pr[jr], vr[cc], Oc[jr][cc]);
        }
    }

    // epilogue: O /= l, write ctx [t][h*128+d]
    #pragma unroll
    for (int jr = 0; jr < 4; jr++) {
        float inv = 1.0f / l_i[jr];
        int row = qbase + (ty << 2) + jr;
        float* op = Ctx + (size_t)row * D_MODEL + h * DH;
        float4 o0 = make_float4(Oc[jr][0]*inv, Oc[jr][1]*inv, Oc[jr][2]*inv, Oc[jr][3]*inv);
        float4 o1 = make_float4(Oc[jr][4]*inv, Oc[jr][5]*inv, Oc[jr][6]*inv, Oc[jr][7]*inv);
        *(float4*)&op[(tx << 2)] = o0;
        *(float4*)&op[64 + (tx << 2)] = o1;
    }
}

// ---------------------------------------------------------------------------
// kernel_launch
// ---------------------------------------------------------------------------
extern "C" void kernel_launch(void* const* d_in, const int* in_sizes, int n_in,
                              void* d_out, int out_size)
{
    const float* x  = (const float*)d_in[0];
    const float* WQ = (const float*)d_in[1];
    const float* WK = (const float*)d_in[2];
    const float* WV = (const float*)d_in[3];
    const float* WO = (const float*)d_in[4];
    float* out = (float*)d_out;

    float *qp, *kp, *vp, *cp;
    cudaGetSymbolAddress((void**)&qp, g_Q);
    cudaGetSymbolAddress((void**)&kp, g_K);
    cudaGetSymbolAddress((void**)&vp, g_V);
    cudaGetSymbolAddress((void**)&cp, g_C);

    cudaFuncSetAttribute(flash_kernel,
                         cudaFuncAttributeMaxDynamicSharedMemorySize,
                         FLASH_SMEM_BYTES);

    // Projections: Q/K d-major (transposed epilogue), V row-major
    sgemm128<1><<<dim3(D_MODEL/128, T_SEQ/128), 256>>>(x, WQ, qp, T_SEQ, D_MODEL, D_MODEL);
    sgemm128<1><<<dim3(DKV/128,     T_SEQ/128), 256>>>(x, WK, kp, T_SEQ, DKV,     D_MODEL);
    sgemm128<0><<<dim3(DKV/128,     T_SEQ/128), 256>>>(x, WV, vp, T_SEQ, DKV,     D_MODEL);

    // RoPE on Q and K
    {
        int total = (NH + NKV) * (DH / 2) * T_SEQ;
        rope_kernel<<<(total + 255) / 256, 256>>>(qp, kp);
    }

    // Attention
    flash_kernel<<<dim3(T_SEQ/64, NH), 256, FLASH_SMEM_BYTES>>>(qp, kp, vp, cp);

    // Output projection
    sgemm128<0><<<dim3(D_MODEL/128, T_SEQ/128), 256>>>(cp, WO, out, T_SEQ, D_MODEL, D_MODEL);
}